// round 11
// baseline (speedup 1.0000x reference)
#include <cuda_runtime.h>
#include <cuda_fp16.h>

// CapsuleLayer dynamic routing, GB300 sm_103a.
// B=64, I=2048, Din=16, J=32, D=32, 3 routing iters.
//
// uhat: per-i GEMM with M=batch(64), N=rows(1024=j*32+d), K=16 on HMMA
// (mma.sync.m16n8k16). A = x (4 cached frags), B = W (ldmatrix.x2 per
// 8-row tile). Accumulator fragment holds 2 consecutive d's for a fixed b ->
// pack f16x2 and store DIRECTLY from registers into g_U[b][i][row]
// (no staging smem, no stmatrix, no syncwarp).
// Routes: 6-stage block-wide cp.async ring; partial-reduce buffer aliased
// onto ring stages 0-1 (drained before use).

#define BB 64
#define II 2048
#define CC 16
#define JJ 32
#define DD 32
#define NTILE 16   // i-tiles (blocks) per b; block covers 128 i
#define NSTAGE 6   // cp.async ring stages (8 i = 16KB per stage)
#define NITER 16   // stages per block (128 i / 8)

typedef unsigned long long u64;
typedef unsigned int u32;

__device__ __half g_U[(size_t)BB * II * JJ * DD];   // 256 MB scratch (fp16)
__device__ float g_osum[BB * JJ * DD];              // running output sum
__device__ float g_spart[NTILE][BB * JJ * DD];      // per-itile partial s

// ---------- cp.async helpers ----------
__device__ __forceinline__ void cpasync16(unsigned smem_addr, const void* g) {
    asm volatile("cp.async.cg.shared.global [%0], [%1], 16;" ::"r"(smem_addr),
                 "l"(g));
}
__device__ __forceinline__ void cpcommit() {
    asm volatile("cp.async.commit_group;");
}
template <int N>
__device__ __forceinline__ void cpwait() {
    asm volatile("cp.async.wait_group %0;" ::"n"(N));
}

// ---------- mma helpers ----------
__device__ __forceinline__ void ldmx4(u32& a0, u32& a1, u32& a2, u32& a3,
                                      u32 addr) {
    asm volatile("ldmatrix.sync.aligned.m8n8.x4.shared.b16 {%0,%1,%2,%3}, [%4];"
                 : "=r"(a0), "=r"(a1), "=r"(a2), "=r"(a3)
                 : "r"(addr));
}
__device__ __forceinline__ void ldmx2(u32& b0, u32& b1, u32 addr) {
    asm volatile("ldmatrix.sync.aligned.m8n8.x2.shared.b16 {%0,%1}, [%2];"
                 : "=r"(b0), "=r"(b1)
                 : "r"(addr));
}
__device__ __forceinline__ void mma16816(float& d0, float& d1, float& d2,
                                         float& d3, u32 a0, u32 a1, u32 a2,
                                         u32 a3, u32 b0, u32 b1) {
    const float z = 0.f;
    asm volatile(
        "mma.sync.aligned.m16n8k16.row.col.f32.f16.f16.f32 "
        "{%0,%1,%2,%3}, {%4,%5,%6,%7}, {%8,%9}, {%10,%11,%12,%13};"
        : "=f"(d0), "=f"(d1), "=f"(d2), "=f"(d3)
        : "r"(a0), "r"(a1), "r"(a2), "r"(a3), "r"(b0), "r"(b1), "f"(z), "f"(z),
          "f"(z), "f"(z));
}
__device__ __forceinline__ u32 cvtpack(float lo, float hi) {
    u32 h;
    asm("cvt.rn.f16x2.f32 %0, %1, %2;" : "=r"(h) : "f"(hi), "f"(lo));
    return h;
}

// smem layout for uhat (bytes): 48B row stride -> conflict-free ldmatrix
#define SW_OFF 0                 // W fp16 [1024 rows][48B stride]
#define SX_OFF 49152             // x fp16 [64 rows][48B stride]
#define UHAT_SMEM (SX_OFF + 64 * 48)  // 52224

// ---------------------------------------------------------------------------
// Kernel A (HMMA, direct-store): u_hat[b][i][row] = sum_c W[row,c]*x[b,c].
// One block per i, 8 warps; warp w owns row-tiles (8 rows) w*16..w*16+15,
// loops bt over 4 batch-tiles of 16. Output stored straight from fragments.
// ---------------------------------------------------------------------------
__global__ void __launch_bounds__(256)
uhat_kernel(const float* __restrict__ x, const float* __restrict__ W) {
    extern __shared__ __align__(16) char smraw[];
    const int i = blockIdx.x;
    const int t = threadIdx.x;
    const int w = t >> 5, L = t & 31;

    // ---- stage W_i (1024 rows x 16 c) fp32->fp16 ----
    const float4* Wg = reinterpret_cast<const float4*>(W);
    #pragma unroll
    for (int k = 0; k < 16; k++) {
        int v = t + 256 * k;
        int row = v >> 2, ch = v & 3;  // row = j*32+d
        float4 f = Wg[(size_t)((row >> 5) * II + i) * 128 + (row & 31) * 4 + ch];
        __half2* p = reinterpret_cast<__half2*>(smraw + SW_OFF + row * 48 + ch * 8);
        p[0] = __floats2half2_rn(f.x, f.y);
        p[1] = __floats2half2_rn(f.z, f.w);
    }
    // ---- stage x_i (64 b x 16 c) fp32->fp16 ----
    {
        int b = t >> 2, ch = t & 3;
        float4 f = reinterpret_cast<const float4*>(x)[(size_t)(b * II + i) * 4 + ch];
        __half2* p = reinterpret_cast<__half2*>(smraw + SX_OFF + b * 48 + ch * 8);
        p[0] = __floats2half2_rn(f.x, f.y);
        p[1] = __floats2half2_rn(f.z, f.w);
    }
    __syncthreads();

    const unsigned sbase = (unsigned)__cvta_generic_to_shared(smraw);

    // ---- A fragments (x): 4 batch-tiles of 16, cached in registers ----
    u32 af[4][4];
    #pragma unroll
    for (int bt = 0; bt < 4; bt++) {
        unsigned addr = sbase + SX_OFF + (unsigned)((bt * 16 + (L & 15)) * 48) +
                        ((L & 16) ? 16u : 0u);
        ldmx4(af[bt][0], af[bt][1], af[bt][2], af[bt][3], addr);
    }

    char* gout = reinterpret_cast<char*>(g_U) + (size_t)i * 2048;
    const int bq = L >> 2;           // fragment row group (b offset 0..7)
    const unsigned colb = (L & 3) * 4;  // byte offset of d-pair within row-tile

    #pragma unroll
    for (int rr = 0; rr < 16; rr++) {
        const int rt = w * 16 + rr;  // rows rt*8 .. rt*8+7
        u32 b0, b1;
        ldmx2(b0, b1,
              sbase + SW_OFF + (unsigned)((rt * 8 + (L & 7)) * 48) +
                  ((L & 8) ? 16u : 0u));
        #pragma unroll
        for (int bt = 0; bt < 4; bt++) {
            float d0, d1, d2, d3;
            mma16816(d0, d1, d2, d3, af[bt][0], af[bt][1], af[bt][2], af[bt][3],
                     b0, b1);
            int blo = bt * 16 + bq;
            *reinterpret_cast<u32*>(gout + (size_t)blo * (II * 2048) + rt * 16 +
                                    colb) = cvtpack(d0, d1);
            *reinterpret_cast<u32*>(gout + (size_t)(blo + 8) * (II * 2048) +
                                    rt * 16 + colb) = cvtpack(d2, d3);
        }
    }
}

// ---------------------------------------------------------------------------
// Route compute step: lane l chunk m (uint4 = 8 halfs) holds j = 8m + (l>>2),
// d-seg (l&3)*8..+7. Logit reduce over 4-lane groups; softmax over 32 j via
// in-thread + xor 4,8,16. (Round-9, unchanged.)
// ---------------------------------------------------------------------------
__device__ __forceinline__ void cvt8(const uint4& r, float* uf) {
    const __half2* h = reinterpret_cast<const __half2*>(&r);
    #pragma unroll
    for (int p = 0; p < 4; p++) {
        float2 f = __half22float2(h[p]);
        uf[2 * p] = f.x;
        uf[2 * p + 1] = f.y;
    }
}

template <int MODE>
__device__ __forceinline__ void route_step(const uint4* r, const float ov[4][8],
                                           float sacc[4][8]) {
    float uf[4][8];
    #pragma unroll
    for (int m = 0; m < 4; m++) cvt8(r[m], uf[m]);
    float c[4];
    if (MODE == 0) {
        #pragma unroll
        for (int m = 0; m < 4; m++) c[m] = 0.03125f;
    } else {
        float tp[4];
        #pragma unroll
        for (int m = 0; m < 4; m++) {
            float a = uf[m][0] * ov[m][0];
            #pragma unroll
            for (int k = 1; k < 8; k++) a = fmaf(uf[m][k], ov[m][k], a);
            tp[m] = a;
        }
        #pragma unroll
        for (int s = 1; s < 4; s <<= 1)
            #pragma unroll
            for (int m = 0; m < 4; m++)
                tp[m] += __shfl_xor_sync(0xffffffffu, tp[m], s);
        float e[4], ss = 0.f;
        #pragma unroll
        for (int m = 0; m < 4; m++) {
            e[m] = __expf(tp[m]);
            ss += e[m];
        }
        ss += __shfl_xor_sync(0xffffffffu, ss, 4);
        ss += __shfl_xor_sync(0xffffffffu, ss, 8);
        ss += __shfl_xor_sync(0xffffffffu, ss, 16);
        float inv = __fdividef(1.0f, ss);
        #pragma unroll
        for (int m = 0; m < 4; m++) c[m] = e[m] * inv;
    }
    #pragma unroll
    for (int m = 0; m < 4; m++)
        #pragma unroll
        for (int k = 0; k < 8; k++) sacc[m][k] = fmaf(c[m], uf[m][k], sacc[m][k]);
}

// ---------------------------------------------------------------------------
// Kernel B: one routing pass, 6-stage block-wide cp.async ring. The final
// partial-reduce buffer aliases ring stages 0-1 (all copies drained first).
// ---------------------------------------------------------------------------
template <int MODE, int DIR>
__global__ void __launch_bounds__(256, 2) route_kernel() {
    extern __shared__ __align__(16) char dsm[];
    __half* sU = reinterpret_cast<__half*>(dsm);     // NSTAGE * 16KB
    float* sS = reinterpret_cast<float*>(dsm);       // aliases stages 0-1

    const int itile = DIR ? (NTILE - 1 - (int)blockIdx.x) : (int)blockIdx.x;
    const int b = DIR ? (BB - 1 - (int)blockIdx.y) : (int)blockIdx.y;
    const int t = threadIdx.x, w = t >> 5, l = t & 31;

    float ov[4][8];
    if (MODE > 0) {
        const float4* op = reinterpret_cast<const float4*>(g_osum + b * (JJ * DD));
        #pragma unroll
        for (int m = 0; m < 4; m++) {
            float4 f0 = op[m * 64 + 2 * l], f1 = op[m * 64 + 2 * l + 1];
            ov[m][0] = f0.x; ov[m][1] = f0.y; ov[m][2] = f0.z; ov[m][3] = f0.w;
            ov[m][4] = f1.x; ov[m][5] = f1.y; ov[m][6] = f1.z; ov[m][7] = f1.w;
        }
    }
    float sacc[4][8];
    #pragma unroll
    for (int m = 0; m < 4; m++)
        #pragma unroll
        for (int k = 0; k < 8; k++) sacc[m][k] = 0.f;

    const char* gbt = reinterpret_cast<const char*>(g_U) +
                      ((size_t)b * II + itile * 128) * 2048 + (size_t)t * 16;
    const unsigned su_base =
        (unsigned)__cvta_generic_to_shared(sU) + (unsigned)(t * 16);

    #pragma unroll
    for (int s = 0; s < NSTAGE - 1; s++) {
        #pragma unroll
        for (int k = 0; k < 4; k++)
            cpasync16(su_base + (unsigned)(s * 16384 + k * 4096),
                      gbt + (size_t)s * 16384 + k * 4096);
        cpcommit();
    }

    int rd = 0;
    int wr = NSTAGE - 1;
    for (int it = 0; it < NITER; it++) {
        cpwait<NSTAGE - 2>();
        __syncthreads();
        const uint4* p =
            reinterpret_cast<const uint4*>(sU + rd * 8192 + w * 1024);
        uint4 r[4];
        #pragma unroll
        for (int m = 0; m < 4; m++) r[m] = p[m * 32 + l];
        route_step<MODE>(r, ov, sacc);
        __syncthreads();
        {
            int s = it + NSTAGE - 1;
            if (s < NITER) {
                #pragma unroll
                for (int k = 0; k < 4; k++)
                    cpasync16(su_base + (unsigned)(wr * 16384 + k * 4096),
                              gbt + (size_t)s * 16384 + k * 4096);
            }
            cpcommit();
        }
        if (++rd == NSTAGE) rd = 0;
        if (++wr == NSTAGE) wr = 0;
    }

    cpwait<0>();       // drain everything before aliasing stages 0-1 as sS
    __syncthreads();

    float4* sp = reinterpret_cast<float4*>(sS + w * 1024);
    #pragma unroll
    for (int m = 0; m < 4; m++) {
        sp[(m * 32 + l) * 2 + 0] =
            make_float4(sacc[m][0], sacc[m][1], sacc[m][2], sacc[m][3]);
        sp[(m * 32 + l) * 2 + 1] =
            make_float4(sacc[m][4], sacc[m][5], sacc[m][6], sacc[m][7]);
    }
    __syncthreads();
    for (int idx = t; idx < JJ * DD; idx += 256) {
        float v = 0.f;
        #pragma unroll
        for (int ww = 0; ww < 8; ww++) v += sS[ww * 1024 + idx];
        g_spart[itile][b * (JJ * DD) + idx] = v;
    }
}

// ---------------------------------------------------------------------------
// Kernel C: reduce itile partials, squash, update osum / write final out.
// ---------------------------------------------------------------------------
__global__ void __launch_bounds__(256) squash_kernel(float* __restrict__ out,
                                                     int mode) {
    const int t = threadIdx.x;
    const int bj = blockIdx.x * 8 + (t >> 5);
    const int l = t & 31;
    float v = 0.f;
    #pragma unroll
    for (int it = 0; it < NTILE; it++) v += g_spart[it][bj * DD + l];
    float s2 = v * v;
    #pragma unroll
    for (int s = 1; s < 32; s <<= 1) s2 += __shfl_xor_sync(0xffffffffu, s2, s);
    float scale = (s2 / (1.0f + s2)) * rsqrtf(s2 + 1e-7f);
    float o = scale * v;
    if (mode == 2)
        out[bj * DD + l] = o;
    else if (mode == 1)
        g_osum[bj * DD + l] += o;
    else
        g_osum[bj * DD + l] = o;
}

// ---------------------------------------------------------------------------
extern "C" void kernel_launch(void* const* d_in, const int* in_sizes, int n_in,
                              void* d_out, int out_size) {
    const float* x;
    const float* W;
    if (in_sizes[0] == BB * II * CC) {
        x = (const float*)d_in[0];
        W = (const float*)d_in[1];
    } else {
        x = (const float*)d_in[1];
        W = (const float*)d_in[0];
    }

    const int uhat_smem = UHAT_SMEM;            // 52224
    const int route_smem = NSTAGE * 16384;      // 98304
    cudaFuncSetAttribute(uhat_kernel, cudaFuncAttributeMaxDynamicSharedMemorySize,
                         uhat_smem);
    cudaFuncSetAttribute(route_kernel<0, 1>,
                         cudaFuncAttributeMaxDynamicSharedMemorySize, route_smem);
    cudaFuncSetAttribute(route_kernel<1, 0>,
                         cudaFuncAttributeMaxDynamicSharedMemorySize, route_smem);
    cudaFuncSetAttribute(route_kernel<2, 1>,
                         cudaFuncAttributeMaxDynamicSharedMemorySize, route_smem);

    float* out = (float*)d_out;
    uhat_kernel<<<II, 256, uhat_smem>>>(x, W);
    route_kernel<0, 1><<<dim3(NTILE, BB), 256, route_smem>>>();
    squash_kernel<<<BB * JJ / 8, 256>>>(out, 0);
    route_kernel<1, 0><<<dim3(NTILE, BB), 256, route_smem>>>();
    squash_kernel<<<BB * JJ / 8, 256>>>(out, 1);
    route_kernel<2, 1><<<dim3(NTILE, BB), 256, route_smem>>>();
    squash_kernel<<<BB * JJ / 8, 256>>>(out, 2);
}

// round 12
// speedup vs baseline: 1.5494x; 1.5494x over previous
#include <cuda_runtime.h>
#include <cuda_fp16.h>

// CapsuleLayer dynamic routing, GB300 sm_103a.
// B=64, I=2048, Din=16, J=32, D=32, 3 routing iters.
//
// uhat: scalar fma2 kernel (round-9 proven). Routes: 5-stage block-wide
// cp.async ring; inter-pass squash inlined into route<1>/<2> prologues,
// issued AFTER the ring prologue so it overlaps the DRAM fill. Redundant
// post-consume barrier removed (sync-at-next-iter already orders reuse).
// g_spart double-buffered: r0->[0], r1 [0]->[1], r2 [1]->[0], squash reads [0].

#define BB 64
#define II 2048
#define CC 16
#define JJ 32
#define DD 32
#define NTILE 16   // i-tiles (blocks) per b; block covers 128 i
#define NSTAGE 5   // cp.async ring stages (8 i = 16KB per stage)
#define NITER 16   // stages per block (128 i / 8)

typedef unsigned long long u64;

__device__ __half g_U[(size_t)BB * II * JJ * DD];    // 256 MB scratch (fp16)
__device__ float g_osum[BB * JJ * DD];               // osum persisted by r1
__device__ float g_spart[2][NTILE][BB * JJ * DD];    // double-buffered partials

// ---------- packed fp32x2 helpers ----------
__device__ __forceinline__ u64 fma2(u64 a, u64 b, u64 c) {
    u64 d;
    asm("fma.rn.f32x2 %0, %1, %2, %3;" : "=l"(d) : "l"(a), "l"(b), "l"(c));
    return d;
}
__device__ __forceinline__ u64 add2(u64 a, u64 b) {
    u64 d;
    asm("add.rn.f32x2 %0, %1, %2;" : "=l"(d) : "l"(a), "l"(b));
    return d;
}
__device__ __forceinline__ float hsum2(u64 v) {
    float a, b;
    asm("mov.b64 {%0, %1}, %2;" : "=f"(a), "=f"(b) : "l"(v));
    return a + b;
}

// ---------- cp.async helpers ----------
__device__ __forceinline__ void cpasync16(unsigned smem_addr, const void* g) {
    asm volatile("cp.async.cg.shared.global [%0], [%1], 16;" ::"r"(smem_addr),
                 "l"(g));
}
__device__ __forceinline__ void cpcommit() {
    asm volatile("cp.async.commit_group;");
}
template <int N>
__device__ __forceinline__ void cpwait() {
    asm volatile("cp.async.wait_group %0;" ::"n"(N));
}

// ---------------------------------------------------------------------------
// Kernel A: u_hat[b][i][j][d] = sum_c W[j][i][d][c] * x[b][i][c], fp16.
// One block per i. W chunk-major in smem (8 contiguous LDS.128 per (j,thread),
// conflict-free). Thread (bg = t>>4, q = t&15): 4 batches, d = 2q, 2q+1.
// (Round-9 proven, unchanged.)
// ---------------------------------------------------------------------------
__global__ void __launch_bounds__(256, 2)
uhat_kernel(const float* __restrict__ x, const float* __restrict__ W) {
    extern __shared__ __align__(16) char smraw[];
    float2* sW = reinterpret_cast<float2*>(smraw);        // [8][1024] = 64KB
    float* sX = reinterpret_cast<float*>(smraw + 65536);  // [64][16]  = 4KB
    const int i = blockIdx.x;
    const int t = threadIdx.x;

    const float4* Wg = reinterpret_cast<const float4*>(W);
    #pragma unroll
    for (int k = 0; k < 16; k++) {
        int v = t + 256 * k;
        int row = v >> 2, ch = v & 3;  // row = j*32 + d
        int j = row >> 5, d = row & 31;
        float4 f = Wg[(size_t)(j * II + i) * 128 + d * 4 + ch];
        sW[(2 * ch) * 1024 + row] = make_float2(f.x, f.y);
        sW[(2 * ch + 1) * 1024 + row] = make_float2(f.z, f.w);
    }
    {
        int b = t >> 2, r = t & 3;
        reinterpret_cast<float4*>(sX)[t] =
            reinterpret_cast<const float4*>(x)[(size_t)(b * II + i) * 4 + r];
    }
    __syncthreads();

    const int bg = t >> 4, q = t & 15;
    u64 xr[4][8];
    #pragma unroll
    for (int s = 0; s < 4; s++) {
        const u64* xp = reinterpret_cast<const u64*>(sX + (bg + 16 * s) * CC);
        #pragma unroll
        for (int k = 0; k < 8; k++) xr[s][k] = xp[k];
    }

    __half2* Uo = reinterpret_cast<__half2*>(g_U);
    const float4* sW4 = reinterpret_cast<const float4*>(sW);
    for (int j = 0; j < JJ; j++) {
        u64 w0[8], w1[8];
        #pragma unroll
        for (int k = 0; k < 8; k++) {
            float4 wv = sW4[k * 512 + j * 16 + q];
            const u64* pv = reinterpret_cast<const u64*>(&wv);
            w0[k] = pv[0];  // d = 2q
            w1[k] = pv[1];  // d = 2q+1
        }
        #pragma unroll
        for (int s = 0; s < 4; s++) {
            u64 a0 = 0ULL, a1 = 0ULL, b0 = 0ULL, b1 = 0ULL;
            #pragma unroll
            for (int k = 0; k < 8; k += 2) {
                a0 = fma2(w0[k],     xr[s][k],     a0);
                a1 = fma2(w0[k + 1], xr[s][k + 1], a1);
                b0 = fma2(w1[k],     xr[s][k],     b0);
                b1 = fma2(w1[k + 1], xr[s][k + 1], b1);
            }
            float d0 = hsum2(add2(a0, a1));
            float d1 = hsum2(add2(b0, b1));
            int b = bg + 16 * s;
            Uo[(size_t)(b * II + i) * 512 + j * 16 + q] = __floats2half2_rn(d0, d1);
        }
    }
}

// ---------------------------------------------------------------------------
// Route compute step: lane l chunk m (uint4 = 8 halfs) holds j = 8m + (l>>2),
// d-seg (l&3)*8..+7. Logit reduce over 4-lane groups; softmax over 32 j via
// in-thread + xor 4,8,16.
// ---------------------------------------------------------------------------
__device__ __forceinline__ void cvt8(const uint4& r, float* uf) {
    const __half2* h = reinterpret_cast<const __half2*>(&r);
    #pragma unroll
    for (int p = 0; p < 4; p++) {
        float2 f = __half22float2(h[p]);
        uf[2 * p] = f.x;
        uf[2 * p + 1] = f.y;
    }
}

template <int MODE>
__device__ __forceinline__ void route_step(const uint4* r, const float ov[4][8],
                                           float sacc[4][8]) {
    float uf[4][8];
    #pragma unroll
    for (int m = 0; m < 4; m++) cvt8(r[m], uf[m]);
    float c[4];
    if (MODE == 0) {
        #pragma unroll
        for (int m = 0; m < 4; m++) c[m] = 0.03125f;
    } else {
        float tp[4];
        #pragma unroll
        for (int m = 0; m < 4; m++) {
            float a = uf[m][0] * ov[m][0];
            #pragma unroll
            for (int k = 1; k < 8; k++) a = fmaf(uf[m][k], ov[m][k], a);
            tp[m] = a;
        }
        #pragma unroll
        for (int s = 1; s < 4; s <<= 1)
            #pragma unroll
            for (int m = 0; m < 4; m++)
                tp[m] += __shfl_xor_sync(0xffffffffu, tp[m], s);
        float e[4], ss = 0.f;
        #pragma unroll
        for (int m = 0; m < 4; m++) {
            e[m] = __expf(tp[m]);
            ss += e[m];
        }
        ss += __shfl_xor_sync(0xffffffffu, ss, 4);
        ss += __shfl_xor_sync(0xffffffffu, ss, 8);
        ss += __shfl_xor_sync(0xffffffffu, ss, 16);
        float inv = __fdividef(1.0f, ss);
        #pragma unroll
        for (int m = 0; m < 4; m++) c[m] = e[m] * inv;
    }
    #pragma unroll
    for (int m = 0; m < 4; m++)
        #pragma unroll
        for (int k = 0; k < 8; k++) sacc[m][k] = fmaf(c[m], uf[m][k], sacc[m][k]);
}

// ---------------------------------------------------------------------------
// Kernel B: one routing pass, 5-stage block-wide cp.async ring.
// Prologue copies issued FIRST; the inline inter-pass squash (MODE>0) runs
// under the DRAM fill. One barrier per loop iteration (post-consume barrier
// proven redundant: next iteration's barrier orders slot reuse).
// MODE 0: c=1/32. MODE 1: osum = squash(sum spart[SRC]); itile 0 persists it.
// MODE 2: osum = g_osum + squash(sum spart[SRC]). Partials -> g_spart[DST].
// ---------------------------------------------------------------------------
template <int MODE, int DIR, int SRC, int DST>
__global__ void __launch_bounds__(256, 2) route_kernel() {
    extern __shared__ __align__(16) char dsm[];
    __half* sU = reinterpret_cast<__half*>(dsm);                  // NSTAGE*16KB
    float* sS = reinterpret_cast<float*>(dsm + NSTAGE * 16384);   // 8*1024 f
    float* sO = sS;  // prologue scratch (free until epilogue)

    const int itile = DIR ? (NTILE - 1 - (int)blockIdx.x) : (int)blockIdx.x;
    const int b = DIR ? (BB - 1 - (int)blockIdx.y) : (int)blockIdx.y;
    const int t = threadIdx.x, w = t >> 5, l = t & 31;

    // ---- issue ring prologue FIRST (no dependence on osum) ----
    const char* gbt = reinterpret_cast<const char*>(g_U) +
                      ((size_t)b * II + itile * 128) * 2048 + (size_t)t * 16;
    const unsigned su_base =
        (unsigned)__cvta_generic_to_shared(sU) + (unsigned)(t * 16);
    #pragma unroll
    for (int s = 0; s < NSTAGE - 1; s++) {
        #pragma unroll
        for (int k = 0; k < 4; k++)
            cpasync16(su_base + (unsigned)(s * 16384 + k * 4096),
                      gbt + (size_t)s * 16384 + k * 4096);
        cpcommit();
    }

    // ---- inline inter-pass squash, overlapped with the DRAM fill ----
    float ov[4][8];
    if (MODE > 0) {
        for (int idx = t; idx < JJ * DD; idx += 256) {
            float v = 0.f;
            #pragma unroll
            for (int it = 0; it < NTILE; it++)
                v += g_spart[SRC][it][b * (JJ * DD) + idx];
            sO[idx] = v;
        }
        __syncthreads();
        #pragma unroll
        for (int jj = 0; jj < 4; jj++) {
            int j = w * 4 + jj;
            float v = sO[j * DD + l];
            float s2 = v * v;
            #pragma unroll
            for (int s = 1; s < 32; s <<= 1)
                s2 += __shfl_xor_sync(0xffffffffu, s2, s);
            float scale = (s2 / (1.0f + s2)) * rsqrtf(s2 + 1e-7f);
            float o = scale * v;
            if (MODE == 2) o += g_osum[b * (JJ * DD) + j * DD + l];
            sO[j * DD + l] = o;
        }
        __syncthreads();
        if (MODE == 1 && itile == 0) {
            for (int idx = t; idx < JJ * DD; idx += 256)
                g_osum[b * (JJ * DD) + idx] = sO[idx];
        }
        {
            const float4* op = reinterpret_cast<const float4*>(sO);
            #pragma unroll
            for (int m = 0; m < 4; m++) {
                float4 f0 = op[m * 64 + 2 * l], f1 = op[m * 64 + 2 * l + 1];
                ov[m][0] = f0.x; ov[m][1] = f0.y; ov[m][2] = f0.z; ov[m][3] = f0.w;
                ov[m][4] = f1.x; ov[m][5] = f1.y; ov[m][6] = f1.z; ov[m][7] = f1.w;
            }
        }
    }

    float sacc[4][8];
    #pragma unroll
    for (int m = 0; m < 4; m++)
        #pragma unroll
        for (int k = 0; k < 8; k++) sacc[m][k] = 0.f;

    int rd = 0;
    int wr = NSTAGE - 1;
    for (int it = 0; it < NITER; it++) {
        cpwait<NSTAGE - 2>();  // own copies for stage rd done
        __syncthreads();       // => all threads' copies done; also orders reuse
        const uint4* p =
            reinterpret_cast<const uint4*>(sU + rd * 8192 + w * 1024);
        uint4 r[4];
        #pragma unroll
        for (int m = 0; m < 4; m++) r[m] = p[m * 32 + l];
        route_step<MODE>(r, ov, sacc);
        // refill slot wr (its previous stage was consumed before this
        // iteration's barrier) -- commit EVERY iteration to keep groups aligned
        {
            int s = it + NSTAGE - 1;
            if (s < NITER) {
                #pragma unroll
                for (int k = 0; k < 4; k++)
                    cpasync16(su_base + (unsigned)(wr * 16384 + k * 4096),
                              gbt + (size_t)s * 16384 + k * 4096);
            }
            cpcommit();
        }
        if (++rd == NSTAGE) rd = 0;
        if (++wr == NSTAGE) wr = 0;
    }
    __syncthreads();  // all consumption done before sS reuse

    // block partial reduce (fixed order -> deterministic)
    float4* sp = reinterpret_cast<float4*>(sS + w * 1024);
    #pragma unroll
    for (int m = 0; m < 4; m++) {
        sp[(m * 32 + l) * 2 + 0] =
            make_float4(sacc[m][0], sacc[m][1], sacc[m][2], sacc[m][3]);
        sp[(m * 32 + l) * 2 + 1] =
            make_float4(sacc[m][4], sacc[m][5], sacc[m][6], sacc[m][7]);
    }
    __syncthreads();
    for (int idx = t; idx < JJ * DD; idx += 256) {
        float v = 0.f;
        #pragma unroll
        for (int ww = 0; ww < 8; ww++) v += sS[ww * 1024 + idx];
        g_spart[DST][itile][b * (JJ * DD) + idx] = v;
    }
}

// ---------------------------------------------------------------------------
// Kernel C: final squash -> out (reads g_spart[0], written by route<2>).
// ---------------------------------------------------------------------------
__global__ void __launch_bounds__(256) squash_kernel(float* __restrict__ out) {
    const int t = threadIdx.x;
    const int bj = blockIdx.x * 8 + (t >> 5);
    const int l = t & 31;
    float v = 0.f;
    #pragma unroll
    for (int it = 0; it < NTILE; it++) v += g_spart[0][it][bj * DD + l];
    float s2 = v * v;
    #pragma unroll
    for (int s = 1; s < 32; s <<= 1) s2 += __shfl_xor_sync(0xffffffffu, s2, s);
    float scale = (s2 / (1.0f + s2)) * rsqrtf(s2 + 1e-7f);
    out[bj * DD + l] = scale * v;
}

// ---------------------------------------------------------------------------
extern "C" void kernel_launch(void* const* d_in, const int* in_sizes, int n_in,
                              void* d_out, int out_size) {
    const float* x;
    const float* W;
    if (in_sizes[0] == BB * II * CC) {
        x = (const float*)d_in[0];
        W = (const float*)d_in[1];
    } else {
        x = (const float*)d_in[1];
        W = (const float*)d_in[0];
    }

    const int uhat_smem = 65536 + BB * CC * (int)sizeof(float);            // 69632
    const int route_smem = NSTAGE * 16384 + 8 * 1024 * (int)sizeof(float); // 114688
    cudaFuncSetAttribute(uhat_kernel, cudaFuncAttributeMaxDynamicSharedMemorySize,
                         uhat_smem);
    cudaFuncSetAttribute((const void*)route_kernel<0, 1, 0, 0>,
                         cudaFuncAttributeMaxDynamicSharedMemorySize, route_smem);
    cudaFuncSetAttribute((const void*)route_kernel<1, 0, 0, 1>,
                         cudaFuncAttributeMaxDynamicSharedMemorySize, route_smem);
    cudaFuncSetAttribute((const void*)route_kernel<2, 1, 1, 0>,
                         cudaFuncAttributeMaxDynamicSharedMemorySize, route_smem);

    float* out = (float*)d_out;
    uhat_kernel<<<II, 256, uhat_smem>>>(x, W);
    route_kernel<0, 1, 0, 0><<<dim3(NTILE, BB), 256, route_smem>>>();
    route_kernel<1, 0, 0, 1><<<dim3(NTILE, BB), 256, route_smem>>>();
    route_kernel<2, 1, 1, 0><<<dim3(NTILE, BB), 256, route_smem>>>();
    squash_kernel<<<BB * JJ / 8, 256>>>(out);
}

// round 13
// speedup vs baseline: 1.6642x; 1.0741x over previous
#include <cuda_runtime.h>
#include <cuda_fp16.h>

// CapsuleLayer dynamic routing, GB300 sm_103a.
// B=64, I=2048, Din=16, J=32, D=32, 3 routing iters.
//
// b_k[b,j,i] = osum_k[b,j,:] . u_hat[b,j,i,:]; each routing iteration is one
// streaming pass over fp16 u_hat ([b][i][j][d]) + tiny squash kernel.
// Iteration 0: c == 1/32 exactly. Softmax without max-subtraction.
// Route passes stream u_hat through a 5-stage block-wide cp.async smem ring.
// ONE barrier per ring iteration: the barrier at iter `it` orders all
// consumption of the previous slot before its refill (proof in comments).
// A group is committed EVERY iteration (empty in the tail) so
// wait_group<NSTAGE-2> stays aligned through the epilogue.

#define BB 64
#define II 2048
#define CC 16
#define JJ 32
#define DD 32
#define NTILE 16   // i-tiles (blocks) per b; block covers 128 i
#define NSTAGE 5   // cp.async ring stages (8 i = 16KB per stage)
#define NITER 16   // stages per block (128 i / 8)

typedef unsigned long long u64;

__device__ __half g_U[(size_t)BB * II * JJ * DD];   // 256 MB scratch (fp16)
__device__ float g_osum[BB * JJ * DD];              // running output sum
__device__ float g_spart[NTILE][BB * JJ * DD];      // per-itile partial s

// ---------- packed fp32x2 helpers ----------
__device__ __forceinline__ u64 fma2(u64 a, u64 b, u64 c) {
    u64 d;
    asm("fma.rn.f32x2 %0, %1, %2, %3;" : "=l"(d) : "l"(a), "l"(b), "l"(c));
    return d;
}
__device__ __forceinline__ u64 add2(u64 a, u64 b) {
    u64 d;
    asm("add.rn.f32x2 %0, %1, %2;" : "=l"(d) : "l"(a), "l"(b));
    return d;
}
__device__ __forceinline__ float hsum2(u64 v) {
    float a, b;
    asm("mov.b64 {%0, %1}, %2;" : "=f"(a), "=f"(b) : "l"(v));
    return a + b;
}

// ---------- cp.async helpers ----------
__device__ __forceinline__ void cpasync16(unsigned smem_addr, const void* g) {
    asm volatile("cp.async.cg.shared.global [%0], [%1], 16;" ::"r"(smem_addr),
                 "l"(g));
}
__device__ __forceinline__ void cpcommit() {
    asm volatile("cp.async.commit_group;");
}
template <int N>
__device__ __forceinline__ void cpwait() {
    asm volatile("cp.async.wait_group %0;" ::"n"(N));
}

// ---------------------------------------------------------------------------
// Kernel A: u_hat[b][i][j][d] = sum_c W[j][i][d][c] * x[b][i][c], fp16.
// One block per i. W chunk-major in smem (8 contiguous LDS.128 per (j,thread),
// conflict-free). Thread (bg = t>>4, q = t&15): 4 batches, d = 2q, 2q+1.
// (Round-9 proven, unchanged.)
// ---------------------------------------------------------------------------
__global__ void __launch_bounds__(256, 2)
uhat_kernel(const float* __restrict__ x, const float* __restrict__ W) {
    extern __shared__ __align__(16) char smraw[];
    float2* sW = reinterpret_cast<float2*>(smraw);        // [8][1024] = 64KB
    float* sX = reinterpret_cast<float*>(smraw + 65536);  // [64][16]  = 4KB
    const int i = blockIdx.x;
    const int t = threadIdx.x;

    const float4* Wg = reinterpret_cast<const float4*>(W);
    #pragma unroll
    for (int k = 0; k < 16; k++) {
        int v = t + 256 * k;
        int row = v >> 2, ch = v & 3;  // row = j*32 + d
        int j = row >> 5, d = row & 31;
        float4 f = Wg[(size_t)(j * II + i) * 128 + d * 4 + ch];
        sW[(2 * ch) * 1024 + row] = make_float2(f.x, f.y);
        sW[(2 * ch + 1) * 1024 + row] = make_float2(f.z, f.w);
    }
    {
        int b = t >> 2, r = t & 3;
        reinterpret_cast<float4*>(sX)[t] =
            reinterpret_cast<const float4*>(x)[(size_t)(b * II + i) * 4 + r];
    }
    __syncthreads();

    const int bg = t >> 4, q = t & 15;
    u64 xr[4][8];
    #pragma unroll
    for (int s = 0; s < 4; s++) {
        const u64* xp = reinterpret_cast<const u64*>(sX + (bg + 16 * s) * CC);
        #pragma unroll
        for (int k = 0; k < 8; k++) xr[s][k] = xp[k];
    }

    __half2* Uo = reinterpret_cast<__half2*>(g_U);
    const float4* sW4 = reinterpret_cast<const float4*>(sW);
    for (int j = 0; j < JJ; j++) {
        u64 w0[8], w1[8];
        #pragma unroll
        for (int k = 0; k < 8; k++) {
            float4 wv = sW4[k * 512 + j * 16 + q];
            const u64* pv = reinterpret_cast<const u64*>(&wv);
            w0[k] = pv[0];  // d = 2q
            w1[k] = pv[1];  // d = 2q+1
        }
        #pragma unroll
        for (int s = 0; s < 4; s++) {
            u64 a0 = 0ULL, a1 = 0ULL, b0 = 0ULL, b1 = 0ULL;
            #pragma unroll
            for (int k = 0; k < 8; k += 2) {
                a0 = fma2(w0[k],     xr[s][k],     a0);
                a1 = fma2(w0[k + 1], xr[s][k + 1], a1);
                b0 = fma2(w1[k],     xr[s][k],     b0);
                b1 = fma2(w1[k + 1], xr[s][k + 1], b1);
            }
            float d0 = hsum2(add2(a0, a1));
            float d1 = hsum2(add2(b0, b1));
            int b = bg + 16 * s;
            Uo[(size_t)(b * II + i) * 512 + j * 16 + q] = __floats2half2_rn(d0, d1);
        }
    }
}

// ---------------------------------------------------------------------------
// Route compute step: lane l chunk m (uint4 = 8 halfs) holds j = 8m + (l>>2),
// d-seg (l&3)*8..+7. Logit reduce over 4-lane groups; softmax over 32 j via
// in-thread + xor 4,8,16.
// ---------------------------------------------------------------------------
__device__ __forceinline__ void cvt8(const uint4& r, float* uf) {
    const __half2* h = reinterpret_cast<const __half2*>(&r);
    #pragma unroll
    for (int p = 0; p < 4; p++) {
        float2 f = __half22float2(h[p]);
        uf[2 * p] = f.x;
        uf[2 * p + 1] = f.y;
    }
}

template <int MODE>
__device__ __forceinline__ void route_step(const uint4* r, const float ov[4][8],
                                           float sacc[4][8]) {
    float uf[4][8];
    #pragma unroll
    for (int m = 0; m < 4; m++) cvt8(r[m], uf[m]);
    float c[4];
    if (MODE == 0) {
        #pragma unroll
        for (int m = 0; m < 4; m++) c[m] = 0.03125f;
    } else {
        float tp[4];
        #pragma unroll
        for (int m = 0; m < 4; m++) {
            float a = uf[m][0] * ov[m][0];
            #pragma unroll
            for (int k = 1; k < 8; k++) a = fmaf(uf[m][k], ov[m][k], a);
            tp[m] = a;
        }
        #pragma unroll
        for (int s = 1; s < 4; s <<= 1)
            #pragma unroll
            for (int m = 0; m < 4; m++)
                tp[m] += __shfl_xor_sync(0xffffffffu, tp[m], s);
        float e[4], ss = 0.f;
        #pragma unroll
        for (int m = 0; m < 4; m++) {
            e[m] = __expf(tp[m]);
            ss += e[m];
        }
        ss += __shfl_xor_sync(0xffffffffu, ss, 4);
        ss += __shfl_xor_sync(0xffffffffu, ss, 8);
        ss += __shfl_xor_sync(0xffffffffu, ss, 16);
        float inv = __fdividef(1.0f, ss);
        #pragma unroll
        for (int m = 0; m < 4; m++) c[m] = e[m] * inv;
    }
    #pragma unroll
    for (int m = 0; m < 4; m++)
        #pragma unroll
        for (int k = 0; k < 8; k++) sacc[m][k] = fmaf(c[m], uf[m][k], sacc[m][k]);
}

// ---------------------------------------------------------------------------
// Kernel B: one routing pass with a 5-stage block-wide cp.async pipeline,
// ONE barrier per iteration.
// Safety argument: at iter `it`, the barrier is passed only after every
// thread consumed stage rd-1 (during iter it-1). The refill of slot rd-1
// (= wr at iter it) is issued after this barrier -> consume happens-before
// refill block-wide. cpwait<NSTAGE-2> + barrier orders data arrival.
// ---------------------------------------------------------------------------
template <int MODE, int DIR>
__global__ void __launch_bounds__(256, 2) route_kernel() {
    extern __shared__ __align__(16) char dsm[];
    __half* sU = reinterpret_cast<__half*>(dsm);                  // NSTAGE*16KB
    float* sS = reinterpret_cast<float*>(dsm + NSTAGE * 16384);   // 8*1024 f

    const int itile = DIR ? (NTILE - 1 - (int)blockIdx.x) : (int)blockIdx.x;
    const int b = DIR ? (BB - 1 - (int)blockIdx.y) : (int)blockIdx.y;
    const int t = threadIdx.x, w = t >> 5, l = t & 31;

    float ov[4][8];
    if (MODE > 0) {
        const float4* op = reinterpret_cast<const float4*>(g_osum + b * (JJ * DD));
        #pragma unroll
        for (int m = 0; m < 4; m++) {
            float4 f0 = op[m * 64 + 2 * l], f1 = op[m * 64 + 2 * l + 1];
            ov[m][0] = f0.x; ov[m][1] = f0.y; ov[m][2] = f0.z; ov[m][3] = f0.w;
            ov[m][4] = f1.x; ov[m][5] = f1.y; ov[m][6] = f1.z; ov[m][7] = f1.w;
        }
    }
    float sacc[4][8];
    #pragma unroll
    for (int m = 0; m < 4; m++)
        #pragma unroll
        for (int k = 0; k < 8; k++) sacc[m][k] = 0.f;

    const char* gbt = reinterpret_cast<const char*>(g_U) +
                      ((size_t)b * II + itile * 128) * 2048 + (size_t)t * 16;
    const unsigned su_base =
        (unsigned)__cvta_generic_to_shared(sU) + (unsigned)(t * 16);

    #pragma unroll
    for (int s = 0; s < NSTAGE - 1; s++) {
        #pragma unroll
        for (int k = 0; k < 4; k++)
            cpasync16(su_base + (unsigned)(s * 16384 + k * 4096),
                      gbt + (size_t)s * 16384 + k * 4096);
        cpcommit();
    }

    int rd = 0;
    int wr = NSTAGE - 1;
    for (int it = 0; it < NITER; it++) {
        cpwait<NSTAGE - 2>();  // own copies for stage rd complete
        __syncthreads();       // all threads' copies complete; orders slot reuse
        const uint4* p =
            reinterpret_cast<const uint4*>(sU + rd * 8192 + w * 1024);
        uint4 r[4];
        #pragma unroll
        for (int m = 0; m < 4; m++) r[m] = p[m * 32 + l];
        route_step<MODE>(r, ov, sacc);
        // refill slot wr (consumed before this iteration's barrier);
        // commit EVERY iteration (empty tail) to keep groups aligned
        {
            int s = it + NSTAGE - 1;
            if (s < NITER) {
                #pragma unroll
                for (int k = 0; k < 4; k++)
                    cpasync16(su_base + (unsigned)(wr * 16384 + k * 4096),
                              gbt + (size_t)s * 16384 + k * 4096);
            }
            cpcommit();
        }
        if (++rd == NSTAGE) rd = 0;
        if (++wr == NSTAGE) wr = 0;
    }
    __syncthreads();  // all consumption done before sS write-out below

    // block partial reduce (fixed order -> deterministic)
    float4* sp = reinterpret_cast<float4*>(sS + w * 1024);
    #pragma unroll
    for (int m = 0; m < 4; m++) {
        sp[(m * 32 + l) * 2 + 0] =
            make_float4(sacc[m][0], sacc[m][1], sacc[m][2], sacc[m][3]);
        sp[(m * 32 + l) * 2 + 1] =
            make_float4(sacc[m][4], sacc[m][5], sacc[m][6], sacc[m][7]);
    }
    __syncthreads();
    for (int idx = t; idx < JJ * DD; idx += 256) {
        float v = 0.f;
        #pragma unroll
        for (int ww = 0; ww < 8; ww++) v += sS[ww * 1024 + idx];
        g_spart[itile][b * (JJ * DD) + idx] = v;
    }
}

// ---------------------------------------------------------------------------
// Kernel C: reduce itile partials, squash, update osum / write final out.
// mode 0: osum = o ; mode 1: osum += o ; mode 2: out = o.
// ---------------------------------------------------------------------------
__global__ void __launch_bounds__(256) squash_kernel(float* __restrict__ out,
                                                     int mode) {
    const int t = threadIdx.x;
    const int bj = blockIdx.x * 8 + (t >> 5);
    const int l = t & 31;
    float v = 0.f;
    #pragma unroll
    for (int it = 0; it < NTILE; it++) v += g_spart[it][bj * DD + l];
    float s2 = v * v;
    #pragma unroll
    for (int s = 1; s < 32; s <<= 1) s2 += __shfl_xor_sync(0xffffffffu, s2, s);
    float scale = (s2 / (1.0f + s2)) * rsqrtf(s2 + 1e-7f);
    float o = scale * v;
    if (mode == 2)
        out[bj * DD + l] = o;
    else if (mode == 1)
        g_osum[bj * DD + l] += o;
    else
        g_osum[bj * DD + l] = o;
}

// ---------------------------------------------------------------------------
extern "C" void kernel_launch(void* const* d_in, const int* in_sizes, int n_in,
                              void* d_out, int out_size) {
    const float* x;
    const float* W;
    if (in_sizes[0] == BB * II * CC) {
        x = (const float*)d_in[0];
        W = (const float*)d_in[1];
    } else {
        x = (const float*)d_in[1];
        W = (const float*)d_in[0];
    }

    const int uhat_smem = 65536 + BB * CC * (int)sizeof(float);            // 69632
    const int route_smem = NSTAGE * 16384 + 8 * 1024 * (int)sizeof(float); // 114688
    cudaFuncSetAttribute(uhat_kernel, cudaFuncAttributeMaxDynamicSharedMemorySize,
                         uhat_smem);
    cudaFuncSetAttribute(route_kernel<0, 1>,
                         cudaFuncAttributeMaxDynamicSharedMemorySize, route_smem);
    cudaFuncSetAttribute(route_kernel<1, 0>,
                         cudaFuncAttributeMaxDynamicSharedMemorySize, route_smem);
    cudaFuncSetAttribute(route_kernel<2, 1>,
                         cudaFuncAttributeMaxDynamicSharedMemorySize, route_smem);

    float* out = (float*)d_out;
    uhat_kernel<<<II, 256, uhat_smem>>>(x, W);
    route_kernel<0, 1><<<dim3(NTILE, BB), 256, route_smem>>>();
    squash_kernel<<<BB * JJ / 8, 256>>>(out, 0);
    route_kernel<1, 0><<<dim3(NTILE, BB), 256, route_smem>>>();
    squash_kernel<<<BB * JJ / 8, 256>>>(out, 1);
    route_kernel<2, 1><<<dim3(NTILE, BB), 256, route_smem>>>();
    squash_kernel<<<BB * JJ / 8, 256>>>(out, 2);
}